// round 15
// baseline (speedup 1.0000x reference)
#include <cuda_runtime.h>
#include <cuda_fp16.h>
#include <math.h>
#include <stdint.h>

// ---------------- problem constants ----------------
#define BATCH   4
#define SEQ     4096
#define HID     1024
#define NHEAD   16
#define HD      64
#define CSZ     16
#define MROWS   (BATCH*SEQ)        // 16384
#define NCHUNK  (SEQ/CSZ)          // 256
#define BNCH    (BATCH*NCHUNK)     // 1024
#define KTOT    1024
#define BK      64                 // fp16 K per stage (128 bytes/row)
#define KI      (KTOT/BK)          // 16
#define NSTG    3                  // 96KB -> 2 CTAs/SM
#define STG_BYTES 32768            // A 16KB + B 16KB
#define GEMM_SMEM (NSTG*STG_BYTES)
#define GNSTG   4
#define GATES_STG 20480
#define GATES_SMEM (GNSTG*GATES_STG)

// weight buffer layout (fp16): W_in | W_gate | W_out
#define WG_OFF   (HID*HID)
#define WO_OFF   (HID*HID + 2*NHEAD*HID)
#define WTOT     (2*HID*HID + 2*NHEAD*HID)

// ---------------- scratch ----------------
__device__ __align__(16) __half g_Abuf[(size_t)MROWS*KTOT]; // x -> xn -> h (in place)
__device__ __align__(16) __half g_Wbuf[(size_t)WTOT];
__device__ __align__(16) __half g_xph[(size_t)MROWS*HID];
__device__ float g_a[MROWS*NHEAD];
__device__ float g_beta[MROWS*NHEAD];
__device__ float g_C[BNCH*NHEAD];
__device__ float g_E[BNCH*HID];
__device__ float g_carry[BNCH*HID];
__device__ float g_P2[BATCH*HID*16];
__device__ float g_E2[BATCH*HID*16];
__device__ float g_G2[BATCH*HID*16];

// ---------------- PTX helpers ----------------
__device__ __forceinline__ uint32_t smem_u32(const void* p) {
    uint32_t a;
    asm("{ .reg .u64 t; cvta.to.shared.u64 t, %1; cvt.u32.u64 %0, t; }" : "=r"(a) : "l"(p));
    return a;
}
#define CP_COMMIT() asm volatile("cp.async.commit_group;" ::: "memory")
#define CP_WAIT(N)  asm volatile("cp.async.wait_group %0;" :: "n"(N) : "memory")
__device__ __forceinline__ void cp_async16(uint32_t s, const void* g) {
    asm volatile("cp.async.cg.shared.global [%0], [%1], 16;" :: "r"(s), "l"(g) : "memory");
}
__device__ __forceinline__ void ldsm_x4(uint32_t& r0, uint32_t& r1, uint32_t& r2, uint32_t& r3, uint32_t addr) {
    asm volatile("ldmatrix.sync.aligned.m8n8.x4.shared.b16 {%0,%1,%2,%3}, [%4];"
                 : "=r"(r0), "=r"(r1), "=r"(r2), "=r"(r3) : "r"(addr));
}
__device__ __forceinline__ void mma16816(float& c0, float& c1, float& c2, float& c3,
                                         uint32_t a0, uint32_t a1, uint32_t a2, uint32_t a3,
                                         uint32_t b0, uint32_t b1) {
    asm volatile("mma.sync.aligned.m16n8k16.row.col.f32.f16.f16.f32 "
                 "{%0,%1,%2,%3}, {%4,%5,%6,%7}, {%8,%9}, {%0,%1,%2,%3};"
                 : "+f"(c0), "+f"(c1), "+f"(c2), "+f"(c3)
                 : "r"(a0), "r"(a1), "r"(a2), "r"(a3), "r"(b0), "r"(b1));
}
__device__ __forceinline__ uint32_t swz(uint32_t off) { return off ^ ((off >> 3) & 0x70); }

// ---------------- fp32 -> fp16 conversions ----------------
__global__ __launch_bounds__(256) void convert_half_kernel(
    const float* __restrict__ in, __half* __restrict__ out, int n4)
{
    int g = blockIdx.x * 256 + threadIdx.x;
    if (g >= n4) return;
    float4 v = reinterpret_cast<const float4*>(in)[g];
    union { __half h[4]; uint2 u; } H;
    H.h[0] = __float2half_rn(v.x);
    H.h[1] = __float2half_rn(v.y);
    H.h[2] = __float2half_rn(v.z);
    H.h[3] = __float2half_rn(v.w);
    reinterpret_cast<uint2*>(out)[g] = H.u;
}
__global__ __launch_bounds__(256) void convert_wgo_kernel(
    const float* __restrict__ Wg, const float* __restrict__ Wo,
    __half* __restrict__ out)
{
    int g = blockIdx.x * 256 + threadIdx.x;
    if (g >= (WTOT - WG_OFF) / 4) return;
    int e = g * 4;
    const float* src = (e < 2 * NHEAD * HID) ? (Wg + e) : (Wo + (e - 2 * NHEAD * HID));
    float4 v = *reinterpret_cast<const float4*>(src);
    union { __half h[4]; uint2 u; } H;
    H.h[0] = __float2half_rn(v.x);
    H.h[1] = __float2half_rn(v.y);
    H.h[2] = __float2half_rn(v.z);
    H.h[3] = __float2half_rn(v.w);
    reinterpret_cast<uint2*>(out)[g] = H.u;
}

// ---------------- mma.sync fp16 GEMM: 128x128 tile, 8 warps of 32x64 (R8 config) ----------------
__device__ __forceinline__ void load_stage(const __half* Ag, const __half* Bg,
                                           uint32_t stage_base, int tid, int kit) {
    const __half* Ak = Ag + kit * BK;
    const __half* Bk = Bg + kit * BK;
    uint32_t sa = stage_base;
    uint32_t sbb = stage_base + 16384;
#pragma unroll
    for (int i = 0; i < 4; i++) {
        int u = tid + i * 256;
        int row = u >> 3, c = u & 7;
        uint32_t off = swz((uint32_t)(row * 128 + c * 16));
        cp_async16(sa  + off, Ak + (size_t)row * KTOT + c * 8);
        cp_async16(sbb + off, Bk + (size_t)row * KTOT + c * 8);
    }
}

template<bool HALF_OUT>
__global__ __launch_bounds__(256, 2) void mma_gemm_kernel(
    const __half* __restrict__ A, const __half* __restrict__ B,
    float* __restrict__ C, __half* __restrict__ Ch)
{
    extern __shared__ char smem[];
    const uint32_t sb = smem_u32(smem);
    const int tid = threadIdx.x, wid = tid >> 5, lane = tid & 31;
    const int m0 = blockIdx.y * 128;
    const int n0 = blockIdx.x * 128;
    const int warpM = (wid & 3) * 32;
    const int warpN = (wid >> 2) * 64;

    const __half* Ag = A + (size_t)m0 * KTOT;
    const __half* Bg = B + (size_t)n0 * KTOT;

    float acc[2][8][4];
#pragma unroll
    for (int mi = 0; mi < 2; mi++)
#pragma unroll
        for (int ni = 0; ni < 8; ni++)
#pragma unroll
            for (int q = 0; q < 4; q++) acc[mi][ni][q] = 0.f;

    const int arow = warpM + (lane & 15);
    const int brow = warpN + (lane & 7) + ((lane >> 4) << 3);
    const uint32_t acol_base = (uint32_t)((lane >> 4) << 4);
    const uint32_t bcol_base = (uint32_t)(((lane >> 3) & 1) << 4);

#pragma unroll
    for (int s = 0; s < NSTG - 1; s++) { load_stage(Ag, Bg, sb + s * STG_BYTES, tid, s); CP_COMMIT(); }

    for (int it = 0; it < KI; it++) {
        if (it + NSTG - 1 < KI)
            load_stage(Ag, Bg, sb + ((it + NSTG - 1) % NSTG) * STG_BYTES, tid, it + NSTG - 1);
        CP_COMMIT();
        CP_WAIT(NSTG - 1);
        __syncthreads();

        const uint32_t sa  = sb + (it % NSTG) * STG_BYTES;
        const uint32_t sbb = sa + 16384;
#pragma unroll
        for (int kk = 0; kk < 4; kk++) {
            const uint32_t kByte = (uint32_t)(kk * 32);
            uint32_t a[2][4];
#pragma unroll
            for (int mi = 0; mi < 2; mi++) {
                uint32_t off = swz((uint32_t)((arow + mi * 16) * 128) + kByte + acol_base);
                ldsm_x4(a[mi][0], a[mi][1], a[mi][2], a[mi][3], sa + off);
            }
            uint32_t b[8][2];
#pragma unroll
            for (int nb = 0; nb < 4; nb++) {
                uint32_t off = swz((uint32_t)((brow + nb * 16) * 128) + kByte + bcol_base);
                uint32_t r0, r1, r2, r3;
                ldsm_x4(r0, r1, r2, r3, sbb + off);
                b[nb * 2][0] = r0; b[nb * 2][1] = r1;
                b[nb * 2 + 1][0] = r2; b[nb * 2 + 1][1] = r3;
            }
#pragma unroll
            for (int mi = 0; mi < 2; mi++)
#pragma unroll
                for (int ni = 0; ni < 8; ni++)
                    mma16816(acc[mi][ni][0], acc[mi][ni][1], acc[mi][ni][2], acc[mi][ni][3],
                             a[mi][0], a[mi][1], a[mi][2], a[mi][3], b[ni][0], b[ni][1]);
        }
        __syncthreads();
    }

    const int crow = m0 + warpM + (lane >> 2);
    const int ccol = n0 + warpN + 2 * (lane & 3);
#pragma unroll
    for (int mi = 0; mi < 2; mi++)
#pragma unroll
        for (int ni = 0; ni < 8; ni++) {
            if (HALF_OUT) {
                __half* p0 = Ch + (size_t)(crow + mi * 16) * HID + ccol + ni * 8;
                __half* p1 = p0 + 8 * HID;
                *reinterpret_cast<__half2*>(p0) = __floats2half2_rn(acc[mi][ni][0], acc[mi][ni][1]);
                *reinterpret_cast<__half2*>(p1) = __floats2half2_rn(acc[mi][ni][2], acc[mi][ni][3]);
            } else {
                float* p0 = C + (size_t)(crow + mi * 16) * HID + ccol + ni * 8;
                float* p1 = p0 + 8 * HID;
                *reinterpret_cast<float2*>(p0) = make_float2(acc[mi][ni][0], acc[mi][ni][1]);
                *reinterpret_cast<float2*>(p1) = make_float2(acc[mi][ni][2], acc[mi][ni][3]);
            }
        }
}

// ---------------- LayerNorm (warp per row), fp16 in -> fp16 out ----------------
__global__ __launch_bounds__(256) void ln_kernel(
    const __half* __restrict__ xph, const float* __restrict__ ln_g,
    const float* __restrict__ ln_b, __half* __restrict__ xnh)
{
    int w = threadIdx.x >> 5, lane = threadIdx.x & 31;
    int row = blockIdx.x * 8 + w;
    const uint2* xr = reinterpret_cast<const uint2*>(xph + (size_t)row * HID);
    float v[8][4];
    float s = 0.f, s2 = 0.f;
#pragma unroll
    for (int i = 0; i < 8; i++) {
        union { uint2 u; __half h[4]; } U;
        U.u = xr[lane + 32 * i];
#pragma unroll
        for (int q = 0; q < 4; q++) {
            float f = __half2float(U.h[q]);
            v[i][q] = f;
            s += f; s2 += f * f;
        }
    }
#pragma unroll
    for (int o = 16; o > 0; o >>= 1) {
        s  += __shfl_xor_sync(0xffffffffu, s, o);
        s2 += __shfl_xor_sync(0xffffffffu, s2, o);
    }
    float mu = s * (1.f / HID);
    float rs = rsqrtf(s2 * (1.f / HID) - mu * mu + 1e-5f);
    uint2* xh = reinterpret_cast<uint2*>(xnh + (size_t)row * HID);
#pragma unroll
    for (int i = 0; i < 8; i++) {
        int idx = lane + 32 * i;
        float4 g4 = reinterpret_cast<const float4*>(ln_g)[idx];
        float4 b4 = reinterpret_cast<const float4*>(ln_b)[idx];
        union { uint2 u; __half2 h2[2]; } H;
        H.h2[0] = __floats2half2_rn((v[i][0] - mu) * rs * g4.x + b4.x,
                                    (v[i][1] - mu) * rs * g4.y + b4.y);
        H.h2[1] = __floats2half2_rn((v[i][2] - mu) * rs * g4.z + b4.z,
                                    (v[i][3] - mu) * rs * g4.w + b4.w);
        xh[idx] = H.u;
    }
}

// ---------------- gates via HMMA ----------------
__device__ __forceinline__ void gates_load_stage(const __half* Ag, const __half* Bg,
                                                 uint32_t stage_base, int tid, int kit) {
    const __half* Ak = Ag + kit * BK;
    const __half* Bk = Bg + kit * BK;
    uint32_t sa = stage_base;
    uint32_t sbb = stage_base + 16384;
#pragma unroll
    for (int i = 0; i < 4; i++) {
        int u = tid + i * 256;
        int row = u >> 3, c = u & 7;
        uint32_t off = swz((uint32_t)(row * 128 + c * 16));
        cp_async16(sa + off, Ak + (size_t)row * KTOT + c * 8);
    }
    {
        int row = tid >> 3, c = tid & 7;
        uint32_t off = swz((uint32_t)(row * 128 + c * 16));
        cp_async16(sbb + off, Bk + (size_t)row * KTOT + c * 8);
    }
}

__global__ __launch_bounds__(256) void gates_mma_kernel(
    const __half* __restrict__ A, const __half* __restrict__ Wgh,
    const float* __restrict__ bg, const float* __restrict__ eig,
    float* __restrict__ a_out, float* __restrict__ beta_out)
{
    extern __shared__ char smem[];
    const uint32_t sb = smem_u32(smem);
    const int tid = threadIdx.x, wid = tid >> 5, lane = tid & 31;
    const int m0 = blockIdx.x * 128;
    const int warpM = (wid & 3) * 32;
    const int warpN = (wid >> 2) * 16;

    const __half* Ag = A + (size_t)m0 * KTOT;

    float acc[2][2][4];
#pragma unroll
    for (int mi = 0; mi < 2; mi++)
#pragma unroll
        for (int ni = 0; ni < 2; ni++)
#pragma unroll
            for (int q = 0; q < 4; q++) acc[mi][ni][q] = 0.f;

    const int arow = warpM + (lane & 15);
    const int brow = warpN + (lane & 7) + ((lane >> 4) << 3);
    const uint32_t acol_base = (uint32_t)((lane >> 4) << 4);
    const uint32_t bcol_base = (uint32_t)(((lane >> 3) & 1) << 4);

#pragma unroll
    for (int s = 0; s < GNSTG - 1; s++) { gates_load_stage(Ag, Wgh, sb + s * GATES_STG, tid, s); CP_COMMIT(); }

    for (int it = 0; it < KI; it++) {
        if (it + GNSTG - 1 < KI)
            gates_load_stage(Ag, Wgh, sb + ((it + GNSTG - 1) & 3) * GATES_STG, tid, it + GNSTG - 1);
        CP_COMMIT();
        CP_WAIT(GNSTG - 1);
        __syncthreads();

        const uint32_t sa  = sb + (it & 3) * GATES_STG;
        const uint32_t sbb = sa + 16384;
#pragma unroll
        for (int kk = 0; kk < 4; kk++) {
            const uint32_t kByte = (uint32_t)(kk * 32);
            uint32_t a[2][4];
#pragma unroll
            for (int mi = 0; mi < 2; mi++) {
                uint32_t off = swz((uint32_t)((arow + mi * 16) * 128) + kByte + acol_base);
                ldsm_x4(a[mi][0], a[mi][1], a[mi][2], a[mi][3], sa + off);
            }
            uint32_t b0, b1, b2, b3;
            {
                uint32_t off = swz((uint32_t)(brow * 128) + kByte + bcol_base);
                ldsm_x4(b0, b1, b2, b3, sbb + off);
            }
#pragma unroll
            for (int mi = 0; mi < 2; mi++) {
                mma16816(acc[mi][0][0], acc[mi][0][1], acc[mi][0][2], acc[mi][0][3],
                         a[mi][0], a[mi][1], a[mi][2], a[mi][3], b0, b1);
                mma16816(acc[mi][1][0], acc[mi][1][1], acc[mi][1][2], acc[mi][1][3],
                         a[mi][0], a[mi][1], a[mi][2], a[mi][3], b2, b3);
            }
        }
        __syncthreads();
    }

    const int crow = m0 + warpM + (lane >> 2);
    const int ccol0 = warpN + 2 * (lane & 3);
#pragma unroll
    for (int mi = 0; mi < 2; mi++)
#pragma unroll
        for (int ni = 0; ni < 2; ni++) {
            int g0 = ccol0 + ni * 8;
#pragma unroll
            for (int q = 0; q < 4; q++) {
                int g = g0 + (q & 1);
                int row = crow + mi * 16 + ((q >> 1) << 3);
                float sg = 1.f / (1.f + expf(-(acc[mi][ni][q] + bg[g])));
                if (g < 16) a_out[(size_t)row * NHEAD + g] = tanhf(eig[g]) * sg;
                else        beta_out[(size_t)row * NHEAD + (g - 16)] = sg;
            }
        }
}

// ---------------- scanE: per-chunk Cc/Ee only (4 units per block) ----------------
__global__ __launch_bounds__(256) void scanE_kernel(
    const float* __restrict__ a_buf, const float* __restrict__ beta_buf,
    const __half* __restrict__ xnh,
    float* __restrict__ Cc, float* __restrict__ Ee)
{
    const int unit = threadIdx.x >> 6;
    const int d    = threadIdx.x & 63;
    const int blk  = blockIdx.x * 4 + unit;
    const int h    = blk & 15;
    const int bn   = blk >> 4;
    const int base_pos = bn * CSZ;

    __shared__ float s_cum[4][CSZ], s_inv[4][CSZ], s_beta[4][CSZ];
    __shared__ float s_a[4][CSZ];
    if (d < CSZ) {
        s_a[unit][d]    = a_buf[(size_t)(base_pos + d) * NHEAD + h];
        s_beta[unit][d] = beta_buf[(size_t)(base_pos + d) * NHEAD + h];
    }
    __syncthreads();
    if (d == 0) {
        float c = 1.f;
#pragma unroll
        for (int j = 0; j < CSZ; j++) {
            float cp = c;
            c = c * s_a[unit][j];
            s_cum[unit][j] = c;
            s_inv[unit][j] = (fabsf(cp) > 1e-8f) ? (1.f / cp) : 0.f;
        }
    }
    __syncthreads();

    float Q = 0.f, hc = 0.f;
#pragma unroll
    for (int j = 0; j < CSZ; j++) {
        size_t idx = (size_t)(base_pos + j) * HID + h * HD + d;
        float bv = s_beta[unit][j] * __half2float(xnh[idx]);
        hc = fmaf(s_cum[unit][j], Q, bv);
        Q = fmaf(bv, s_inv[unit][j], Q);
    }
    Ee[(size_t)bn * HID + h * HD + d] = hc;
    if (d == 0) Cc[(size_t)bn * NHEAD + h] = s_cum[unit][CSZ - 1];
}

// ---------------- scan pass 2: 3-phase group scan ----------------
__global__ __launch_bounds__(256) void scan2a_kernel(
    const float* __restrict__ Cc, const float* __restrict__ Ee,
    float* __restrict__ P2, float* __restrict__ E2)
{
    int idx = blockIdx.x * 256 + threadIdx.x;
    int ch = idx & 4095, grp = idx >> 12;
    int b = ch >> 10, c = ch & 1023, h = c >> 6;
    float P = 1.f, E = 0.f;
#pragma unroll
    for (int i = 0; i < 16; i++) {
        int bn = b * NCHUNK + grp * 16 + i;
        float cc = Cc[(size_t)bn * NHEAD + h];
        E = fmaf(cc, E, Ee[(size_t)bn * HID + c]);
        P *= cc;
    }
    P2[idx] = P; E2[idx] = E;
}
__global__ __launch_bounds__(128) void scan2b_kernel(
    const float* __restrict__ P2, const float* __restrict__ E2, float* __restrict__ G2)
{
    int ch = blockIdx.x * 128 + threadIdx.x;
    float car = 0.f;
#pragma unroll
    for (int g = 0; g < 16; g++) {
        G2[g * 4096 + ch] = car;
        car = fmaf(P2[g * 4096 + ch], car, E2[g * 4096 + ch]);
    }
}
__global__ __launch_bounds__(256) void scan2c_kernel(
    const float* __restrict__ Cc, const float* __restrict__ Ee,
    const float* __restrict__ G2, float* __restrict__ carry)
{
    int idx = blockIdx.x * 256 + threadIdx.x;
    int ch = idx & 4095, grp = idx >> 12;
    int b = ch >> 10, c = ch & 1023, h = c >> 6;
    float car = G2[grp * 4096 + ch];
#pragma unroll
    for (int i = 0; i < 16; i++) {
        int bn = b * NCHUNK + grp * 16 + i;
        carry[(size_t)bn * HID + c] = car;
        car = fmaf(Cc[(size_t)bn * NHEAD + h], car, Ee[(size_t)bn * HID + c]);
    }
}

// ---------------- scanB: recurrence with carry -> fp16 h (in place) + h_final ----------------
__global__ __launch_bounds__(256) void scanB_kernel(
    const float* __restrict__ a_buf, const float* __restrict__ beta_buf,
    const float* __restrict__ carry,
    __half* __restrict__ xh, float* __restrict__ h_final)
{
    const int unit = threadIdx.x >> 6;
    const int d    = threadIdx.x & 63;
    const int blk  = blockIdx.x * 4 + unit;
    const int h    = blk & 15;
    const int bn   = blk >> 4;
    const int base_pos = bn * CSZ;

    __shared__ float s_cum[4][CSZ], s_inv[4][CSZ], s_beta[4][CSZ];
    __shared__ float s_a[4][CSZ];
    if (d < CSZ) {
        s_a[unit][d]    = a_buf[(size_t)(base_pos + d) * NHEAD + h];
        s_beta[unit][d] = beta_buf[(size_t)(base_pos + d) * NHEAD + h];
    }
    __syncthreads();
    if (d == 0) {
        float c = 1.f;
#pragma unroll
        for (int j = 0; j < CSZ; j++) {
            float cp = c;
            c = c * s_a[unit][j];
            s_cum[unit][j] = c;
            s_inv[unit][j] = (fabsf(cp) > 1e-8f) ? (1.f / cp) : 0.f;
        }
    }
    __syncthreads();

    float Q = carry[(size_t)bn * HID + h * HD + d];
    float hc = 0.f;
#pragma unroll
    for (int j = 0; j < CSZ; j++) {
        size_t idx = (size_t)(base_pos + j) * HID + h * HD + d;
        float bv = s_beta[unit][j] * __half2float(xh[idx]);
        hc = fmaf(s_cum[unit][j], Q, bv);
        xh[idx] = __float2half_rn(hc);
        Q = fmaf(bv, s_inv[unit][j], Q);
    }
    if ((bn & (NCHUNK - 1)) == NCHUNK - 1) {
        int b = bn >> 8;
        h_final[(size_t)b * HID + h * HD + d] = hc;
    }
}

// ---------------- launch ----------------
extern "C" void kernel_launch(void* const* d_in, const int* in_sizes, int n_in,
                              void* d_out, int out_size)
{
    const float* x       = (const float*)d_in[0];
    const float* W_in    = (const float*)d_in[1];
    const float* ln_g    = (const float*)d_in[2];
    const float* ln_b    = (const float*)d_in[3];
    const float* W_gate  = (const float*)d_in[4];
    const float* b_gate  = (const float*)d_in[5];
    const float* eig_raw = (const float*)d_in[6];
    const float* W_out   = (const float*)d_in[7];

    float* out     = (float*)d_out;
    float* h_final = out + (size_t)MROWS * HID;

    __half *Abuf, *Wbuf, *xph;
    float *ab, *bb, *Cc, *Ee, *carry, *P2, *E2, *G2;
    cudaGetSymbolAddress((void**)&Abuf,  g_Abuf);
    cudaGetSymbolAddress((void**)&Wbuf,  g_Wbuf);
    cudaGetSymbolAddress((void**)&xph,   g_xph);
    cudaGetSymbolAddress((void**)&ab,    g_a);
    cudaGetSymbolAddress((void**)&bb,    g_beta);
    cudaGetSymbolAddress((void**)&Cc,    g_C);
    cudaGetSymbolAddress((void**)&Ee,    g_E);
    cudaGetSymbolAddress((void**)&carry, g_carry);
    cudaGetSymbolAddress((void**)&P2,    g_P2);
    cudaGetSymbolAddress((void**)&E2,    g_E2);
    cudaGetSymbolAddress((void**)&G2,    g_G2);

    cudaFuncSetAttribute(mma_gemm_kernel<true>,  cudaFuncAttributeMaxDynamicSharedMemorySize, GEMM_SMEM);
    cudaFuncSetAttribute(mma_gemm_kernel<false>, cudaFuncAttributeMaxDynamicSharedMemorySize, GEMM_SMEM);
    cudaFuncSetAttribute(gates_mma_kernel, cudaFuncAttributeMaxDynamicSharedMemorySize, GATES_SMEM);

    // launches 0-2: converts (GEMM1 at launch index 3 for ncu)
    convert_half_kernel<<<(HID * HID / 4 + 255) / 256, 256>>>(W_in, Wbuf, HID * HID / 4);
    convert_wgo_kernel<<<((WTOT - WG_OFF) / 4 + 255) / 256, 256>>>(W_gate, W_out, Wbuf + WG_OFF);
    convert_half_kernel<<<(MROWS * HID / 4) / 256, 256>>>(x, Abuf, MROWS * HID / 4);

    // launch 3: GEMM1 -> xph (fp16)
    mma_gemm_kernel<true><<<dim3(HID / 128, MROWS / 128), 256, GEMM_SMEM>>>(Abuf, Wbuf, nullptr, xph);

    // LN -> xn fp16 (in Abuf); gates
    ln_kernel<<<MROWS / 8, 256>>>(xph, ln_g, ln_b, Abuf);
    gates_mma_kernel<<<MROWS / 128, 256, GATES_SMEM>>>(Abuf, Wbuf + WG_OFF, b_gate, eig_raw, ab, bb);

    // chunked scan: Cc/Ee -> carry -> h (in place in Abuf) + h_final
    scanE_kernel<<<BNCH * NHEAD / 4, 256>>>(ab, bb, Abuf, Cc, Ee);
    scan2a_kernel<<<(BATCH * HID * 16) / 256, 256>>>(Cc, Ee, P2, E2);
    scan2b_kernel<<<(BATCH * HID) / 128, 128>>>(P2, E2, G2);
    scan2c_kernel<<<(BATCH * HID * 16) / 256, 256>>>(Cc, Ee, G2, carry);
    scanB_kernel<<<BNCH * NHEAD / 4, 256>>>(ab, bb, carry, Abuf, h_final);

    // GEMM2 -> out (fp32)
    mma_gemm_kernel<false><<<dim3(HID / 128, MROWS / 128), 256, GEMM_SMEM>>>(Abuf, Wbuf + WO_OFF, out, nullptr);
}

// round 16
// speedup vs baseline: 1.0245x; 1.0245x over previous
#include <cuda_runtime.h>
#include <cuda_fp16.h>
#include <math.h>
#include <stdint.h>

// ---------------- problem constants ----------------
#define BATCH   4
#define SEQ     4096
#define HID     1024
#define NHEAD   16
#define HD      64
#define CSZ     16
#define MROWS   (BATCH*SEQ)        // 16384
#define NCHUNK  (SEQ/CSZ)          // 256
#define BNCH    (BATCH*NCHUNK)     // 1024
#define KTOT    1024
#define BK      64                 // fp16 K per stage (128 bytes/row)
#define KI      (KTOT/BK)          // 16
#define NSTG    3                  // 96KB -> 2 CTAs/SM
#define STG_BYTES 32768            // A 16KB + B 16KB
#define GEMM_SMEM (NSTG*STG_BYTES)
#define GNSTG   4
#define GATES_STG 20480
#define GATES_SMEM (GNSTG*GATES_STG)

// weight buffer layout (fp16): W_in | W_gate | W_out
#define WG_OFF   (HID*HID)
#define WO_OFF   (HID*HID + 2*NHEAD*HID)
#define WTOT     (2*HID*HID + 2*NHEAD*HID)

// fused convert partition (float4 indices)
#define XN4      (MROWS*HID/4)     // 4,194,304
#define WIN4     (HID*HID/4)       // 262,144
#define WG4      (2*NHEAD*HID/4)   // 8,192
#define ALL4     (XN4 + WTOT/4)    // 4,726,784

// ---------------- scratch ----------------
__device__ __align__(16) __half g_Abuf[(size_t)MROWS*KTOT]; // x -> xn -> h (in place)
__device__ __align__(16) __half g_Wbuf[(size_t)WTOT];
__device__ __align__(16) __half g_xph[(size_t)MROWS*HID];
__device__ float g_a[MROWS*NHEAD];
__device__ float g_beta[MROWS*NHEAD];
__device__ float g_C[BNCH*NHEAD];
__device__ float g_E[BNCH*HID];
__device__ float g_carry[BNCH*HID];
__device__ float g_P2[BATCH*HID*16];
__device__ float g_E2[BATCH*HID*16];

// ---------------- PTX helpers ----------------
__device__ __forceinline__ uint32_t smem_u32(const void* p) {
    uint32_t a;
    asm("{ .reg .u64 t; cvta.to.shared.u64 t, %1; cvt.u32.u64 %0, t; }" : "=r"(a) : "l"(p));
    return a;
}
#define CP_COMMIT() asm volatile("cp.async.commit_group;" ::: "memory")
#define CP_WAIT(N)  asm volatile("cp.async.wait_group %0;" :: "n"(N) : "memory")
__device__ __forceinline__ void cp_async16(uint32_t s, const void* g) {
    asm volatile("cp.async.cg.shared.global [%0], [%1], 16;" :: "r"(s), "l"(g) : "memory");
}
__device__ __forceinline__ void ldsm_x4(uint32_t& r0, uint32_t& r1, uint32_t& r2, uint32_t& r3, uint32_t addr) {
    asm volatile("ldmatrix.sync.aligned.m8n8.x4.shared.b16 {%0,%1,%2,%3}, [%4];"
                 : "=r"(r0), "=r"(r1), "=r"(r2), "=r"(r3) : "r"(addr));
}
__device__ __forceinline__ void mma16816(float& c0, float& c1, float& c2, float& c3,
                                         uint32_t a0, uint32_t a1, uint32_t a2, uint32_t a3,
                                         uint32_t b0, uint32_t b1) {
    asm volatile("mma.sync.aligned.m16n8k16.row.col.f32.f16.f16.f32 "
                 "{%0,%1,%2,%3}, {%4,%5,%6,%7}, {%8,%9}, {%0,%1,%2,%3};"
                 : "+f"(c0), "+f"(c1), "+f"(c2), "+f"(c3)
                 : "r"(a0), "r"(a1), "r"(a2), "r"(a3), "r"(b0), "r"(b1));
}
__device__ __forceinline__ uint32_t swz(uint32_t off) { return off ^ ((off >> 3) & 0x70); }

// ---------------- fused fp32 -> fp16 conversion: x + W_in + W_gate + W_out ----------------
__global__ __launch_bounds__(256) void convert_all_kernel(
    const float* __restrict__ x, const float* __restrict__ Win,
    const float* __restrict__ Wg, const float* __restrict__ Wo,
    __half* __restrict__ Abuf, __half* __restrict__ Wbuf)
{
    int g = blockIdx.x * 256 + threadIdx.x;
    if (g >= ALL4) return;
    const float* src;
    __half* dst;
    int di;
    if (g < XN4) {
        src = x + g * 4; dst = Abuf; di = g;
    } else {
        int e = g - XN4;
        dst = Wbuf; di = e;
        if (e < WIN4)             src = Win + e * 4;
        else if (e < WIN4 + WG4)  src = Wg + (e - WIN4) * 4;
        else                      src = Wo + (e - WIN4 - WG4) * 4;
    }
    float4 v = *reinterpret_cast<const float4*>(src);
    union { __half h[4]; uint2 u; } H;
    H.h[0] = __float2half_rn(v.x);
    H.h[1] = __float2half_rn(v.y);
    H.h[2] = __float2half_rn(v.z);
    H.h[3] = __float2half_rn(v.w);
    reinterpret_cast<uint2*>(dst)[di] = H.u;
}

// ---------------- mma.sync fp16 GEMM: 128x128 tile, 8 warps of 32x64 (R8 config) ----------------
__device__ __forceinline__ void load_stage(const __half* Ag, const __half* Bg,
                                           uint32_t stage_base, int tid, int kit) {
    const __half* Ak = Ag + kit * BK;
    const __half* Bk = Bg + kit * BK;
    uint32_t sa = stage_base;
    uint32_t sbb = stage_base + 16384;
#pragma unroll
    for (int i = 0; i < 4; i++) {
        int u = tid + i * 256;
        int row = u >> 3, c = u & 7;
        uint32_t off = swz((uint32_t)(row * 128 + c * 16));
        cp_async16(sa  + off, Ak + (size_t)row * KTOT + c * 8);
        cp_async16(sbb + off, Bk + (size_t)row * KTOT + c * 8);
    }
}

template<bool HALF_OUT>
__global__ __launch_bounds__(256, 2) void mma_gemm_kernel(
    const __half* __restrict__ A, const __half* __restrict__ B,
    float* __restrict__ C, __half* __restrict__ Ch)
{
    extern __shared__ char smem[];
    const uint32_t sb = smem_u32(smem);
    const int tid = threadIdx.x, wid = tid >> 5, lane = tid & 31;
    const int m0 = blockIdx.y * 128;
    const int n0 = blockIdx.x * 128;
    const int warpM = (wid & 3) * 32;
    const int warpN = (wid >> 2) * 64;

    const __half* Ag = A + (size_t)m0 * KTOT;
    const __half* Bg = B + (size_t)n0 * KTOT;

    float acc[2][8][4];
#pragma unroll
    for (int mi = 0; mi < 2; mi++)
#pragma unroll
        for (int ni = 0; ni < 8; ni++)
#pragma unroll
            for (int q = 0; q < 4; q++) acc[mi][ni][q] = 0.f;

    const int arow = warpM + (lane & 15);
    const int brow = warpN + (lane & 7) + ((lane >> 4) << 3);
    const uint32_t acol_base = (uint32_t)((lane >> 4) << 4);
    const uint32_t bcol_base = (uint32_t)(((lane >> 3) & 1) << 4);

#pragma unroll
    for (int s = 0; s < NSTG - 1; s++) { load_stage(Ag, Bg, sb + s * STG_BYTES, tid, s); CP_COMMIT(); }

    for (int it = 0; it < KI; it++) {
        if (it + NSTG - 1 < KI)
            load_stage(Ag, Bg, sb + ((it + NSTG - 1) % NSTG) * STG_BYTES, tid, it + NSTG - 1);
        CP_COMMIT();
        CP_WAIT(NSTG - 1);
        __syncthreads();

        const uint32_t sa  = sb + (it % NSTG) * STG_BYTES;
        const uint32_t sbb = sa + 16384;
#pragma unroll
        for (int kk = 0; kk < 4; kk++) {
            const uint32_t kByte = (uint32_t)(kk * 32);
            uint32_t a[2][4];
#pragma unroll
            for (int mi = 0; mi < 2; mi++) {
                uint32_t off = swz((uint32_t)((arow + mi * 16) * 128) + kByte + acol_base);
                ldsm_x4(a[mi][0], a[mi][1], a[mi][2], a[mi][3], sa + off);
            }
            uint32_t b[8][2];
#pragma unroll
            for (int nb = 0; nb < 4; nb++) {
                uint32_t off = swz((uint32_t)((brow + nb * 16) * 128) + kByte + bcol_base);
                uint32_t r0, r1, r2, r3;
                ldsm_x4(r0, r1, r2, r3, sbb + off);
                b[nb * 2][0] = r0; b[nb * 2][1] = r1;
                b[nb * 2 + 1][0] = r2; b[nb * 2 + 1][1] = r3;
            }
#pragma unroll
            for (int mi = 0; mi < 2; mi++)
#pragma unroll
                for (int ni = 0; ni < 8; ni++)
                    mma16816(acc[mi][ni][0], acc[mi][ni][1], acc[mi][ni][2], acc[mi][ni][3],
                             a[mi][0], a[mi][1], a[mi][2], a[mi][3], b[ni][0], b[ni][1]);
        }
        __syncthreads();
    }

    const int crow = m0 + warpM + (lane >> 2);
    const int ccol = n0 + warpN + 2 * (lane & 3);
#pragma unroll
    for (int mi = 0; mi < 2; mi++)
#pragma unroll
        for (int ni = 0; ni < 8; ni++) {
            if (HALF_OUT) {
                __half* p0 = Ch + (size_t)(crow + mi * 16) * HID + ccol + ni * 8;
                __half* p1 = p0 + 8 * HID;
                *reinterpret_cast<__half2*>(p0) = __floats2half2_rn(acc[mi][ni][0], acc[mi][ni][1]);
                *reinterpret_cast<__half2*>(p1) = __floats2half2_rn(acc[mi][ni][2], acc[mi][ni][3]);
            } else {
                float* p0 = C + (size_t)(crow + mi * 16) * HID + ccol + ni * 8;
                float* p1 = p0 + 8 * HID;
                *reinterpret_cast<float2*>(p0) = make_float2(acc[mi][ni][0], acc[mi][ni][1]);
                *reinterpret_cast<float2*>(p1) = make_float2(acc[mi][ni][2], acc[mi][ni][3]);
            }
        }
}

// ---------------- LayerNorm (warp per row), fp16 in -> fp16 out ----------------
__global__ __launch_bounds__(256) void ln_kernel(
    const __half* __restrict__ xph, const float* __restrict__ ln_g,
    const float* __restrict__ ln_b, __half* __restrict__ xnh)
{
    int w = threadIdx.x >> 5, lane = threadIdx.x & 31;
    int row = blockIdx.x * 8 + w;
    const uint2* xr = reinterpret_cast<const uint2*>(xph + (size_t)row * HID);
    float v[8][4];
    float s = 0.f, s2 = 0.f;
#pragma unroll
    for (int i = 0; i < 8; i++) {
        union { uint2 u; __half h[4]; } U;
        U.u = xr[lane + 32 * i];
#pragma unroll
        for (int q = 0; q < 4; q++) {
            float f = __half2float(U.h[q]);
            v[i][q] = f;
            s += f; s2 += f * f;
        }
    }
#pragma unroll
    for (int o = 16; o > 0; o >>= 1) {
        s  += __shfl_xor_sync(0xffffffffu, s, o);
        s2 += __shfl_xor_sync(0xffffffffu, s2, o);
    }
    float mu = s * (1.f / HID);
    float rs = rsqrtf(s2 * (1.f / HID) - mu * mu + 1e-5f);
    uint2* xh = reinterpret_cast<uint2*>(xnh + (size_t)row * HID);
#pragma unroll
    for (int i = 0; i < 8; i++) {
        int idx = lane + 32 * i;
        float4 g4 = reinterpret_cast<const float4*>(ln_g)[idx];
        float4 b4 = reinterpret_cast<const float4*>(ln_b)[idx];
        union { uint2 u; __half2 h2[2]; } H;
        H.h2[0] = __floats2half2_rn((v[i][0] - mu) * rs * g4.x + b4.x,
                                    (v[i][1] - mu) * rs * g4.y + b4.y);
        H.h2[1] = __floats2half2_rn((v[i][2] - mu) * rs * g4.z + b4.z,
                                    (v[i][3] - mu) * rs * g4.w + b4.w);
        xh[idx] = H.u;
    }
}

// ---------------- gates via HMMA ----------------
__device__ __forceinline__ void gates_load_stage(const __half* Ag, const __half* Bg,
                                                 uint32_t stage_base, int tid, int kit) {
    const __half* Ak = Ag + kit * BK;
    const __half* Bk = Bg + kit * BK;
    uint32_t sa = stage_base;
    uint32_t sbb = stage_base + 16384;
#pragma unroll
    for (int i = 0; i < 4; i++) {
        int u = tid + i * 256;
        int row = u >> 3, c = u & 7;
        uint32_t off = swz((uint32_t)(row * 128 + c * 16));
        cp_async16(sa + off, Ak + (size_t)row * KTOT + c * 8);
    }
    {
        int row = tid >> 3, c = tid & 7;
        uint32_t off = swz((uint32_t)(row * 128 + c * 16));
        cp_async16(sbb + off, Bk + (size_t)row * KTOT + c * 8);
    }
}

__global__ __launch_bounds__(256) void gates_mma_kernel(
    const __half* __restrict__ A, const __half* __restrict__ Wgh,
    const float* __restrict__ bg, const float* __restrict__ eig,
    float* __restrict__ a_out, float* __restrict__ beta_out)
{
    extern __shared__ char smem[];
    const uint32_t sb = smem_u32(smem);
    const int tid = threadIdx.x, wid = tid >> 5, lane = tid & 31;
    const int m0 = blockIdx.x * 128;
    const int warpM = (wid & 3) * 32;
    const int warpN = (wid >> 2) * 16;

    const __half* Ag = A + (size_t)m0 * KTOT;

    float acc[2][2][4];
#pragma unroll
    for (int mi = 0; mi < 2; mi++)
#pragma unroll
        for (int ni = 0; ni < 2; ni++)
#pragma unroll
            for (int q = 0; q < 4; q++) acc[mi][ni][q] = 0.f;

    const int arow = warpM + (lane & 15);
    const int brow = warpN + (lane & 7) + ((lane >> 4) << 3);
    const uint32_t acol_base = (uint32_t)((lane >> 4) << 4);
    const uint32_t bcol_base = (uint32_t)(((lane >> 3) & 1) << 4);

#pragma unroll
    for (int s = 0; s < GNSTG - 1; s++) { gates_load_stage(Ag, Wgh, sb + s * GATES_STG, tid, s); CP_COMMIT(); }

    for (int it = 0; it < KI; it++) {
        if (it + GNSTG - 1 < KI)
            gates_load_stage(Ag, Wgh, sb + ((it + GNSTG - 1) & 3) * GATES_STG, tid, it + GNSTG - 1);
        CP_COMMIT();
        CP_WAIT(GNSTG - 1);
        __syncthreads();

        const uint32_t sa  = sb + (it & 3) * GATES_STG;
        const uint32_t sbb = sa + 16384;
#pragma unroll
        for (int kk = 0; kk < 4; kk++) {
            const uint32_t kByte = (uint32_t)(kk * 32);
            uint32_t a[2][4];
#pragma unroll
            for (int mi = 0; mi < 2; mi++) {
                uint32_t off = swz((uint32_t)((arow + mi * 16) * 128) + kByte + acol_base);
                ldsm_x4(a[mi][0], a[mi][1], a[mi][2], a[mi][3], sa + off);
            }
            uint32_t b0, b1, b2, b3;
            {
                uint32_t off = swz((uint32_t)(brow * 128) + kByte + bcol_base);
                ldsm_x4(b0, b1, b2, b3, sbb + off);
            }
#pragma unroll
            for (int mi = 0; mi < 2; mi++) {
                mma16816(acc[mi][0][0], acc[mi][0][1], acc[mi][0][2], acc[mi][0][3],
                         a[mi][0], a[mi][1], a[mi][2], a[mi][3], b0, b1);
                mma16816(acc[mi][1][0], acc[mi][1][1], acc[mi][1][2], acc[mi][1][3],
                         a[mi][0], a[mi][1], a[mi][2], a[mi][3], b2, b3);
            }
        }
        __syncthreads();
    }

    const int crow = m0 + warpM + (lane >> 2);
    const int ccol0 = warpN + 2 * (lane & 3);
#pragma unroll
    for (int mi = 0; mi < 2; mi++)
#pragma unroll
        for (int ni = 0; ni < 2; ni++) {
            int g0 = ccol0 + ni * 8;
#pragma unroll
            for (int q = 0; q < 4; q++) {
                int g = g0 + (q & 1);
                int row = crow + mi * 16 + ((q >> 1) << 3);
                float sg = 1.f / (1.f + expf(-(acc[mi][ni][q] + bg[g])));
                if (g < 16) a_out[(size_t)row * NHEAD + g] = tanhf(eig[g]) * sg;
                else        beta_out[(size_t)row * NHEAD + (g - 16)] = sg;
            }
        }
}

// ---------------- scanE: per-chunk Cc/Ee only (4 units per block) ----------------
__global__ __launch_bounds__(256) void scanE_kernel(
    const float* __restrict__ a_buf, const float* __restrict__ beta_buf,
    const __half* __restrict__ xnh,
    float* __restrict__ Cc, float* __restrict__ Ee)
{
    const int unit = threadIdx.x >> 6;
    const int d    = threadIdx.x & 63;
    const int blk  = blockIdx.x * 4 + unit;
    const int h    = blk & 15;
    const int bn   = blk >> 4;
    const int base_pos = bn * CSZ;

    __shared__ float s_cum[4][CSZ], s_inv[4][CSZ], s_beta[4][CSZ];
    __shared__ float s_a[4][CSZ];
    if (d < CSZ) {
        s_a[unit][d]    = a_buf[(size_t)(base_pos + d) * NHEAD + h];
        s_beta[unit][d] = beta_buf[(size_t)(base_pos + d) * NHEAD + h];
    }
    __syncthreads();
    if (d == 0) {
        float c = 1.f;
#pragma unroll
        for (int j = 0; j < CSZ; j++) {
            float cp = c;
            c = c * s_a[unit][j];
            s_cum[unit][j] = c;
            s_inv[unit][j] = (fabsf(cp) > 1e-8f) ? (1.f / cp) : 0.f;
        }
    }
    __syncthreads();

    float Q = 0.f, hc = 0.f;
#pragma unroll
    for (int j = 0; j < CSZ; j++) {
        size_t idx = (size_t)(base_pos + j) * HID + h * HD + d;
        float bv = s_beta[unit][j] * __half2float(xnh[idx]);
        hc = fmaf(s_cum[unit][j], Q, bv);
        Q = fmaf(bv, s_inv[unit][j], Q);
    }
    Ee[(size_t)bn * HID + h * HD + d] = hc;
    if (d == 0) Cc[(size_t)bn * NHEAD + h] = s_cum[unit][CSZ - 1];
}

// ---------------- scan pass 2: group totals, then fused carry (2b folded into 2c) ----------------
__global__ __launch_bounds__(256) void scan2a_kernel(
    const float* __restrict__ Cc, const float* __restrict__ Ee,
    float* __restrict__ P2, float* __restrict__ E2)
{
    int idx = blockIdx.x * 256 + threadIdx.x;
    int ch = idx & 4095, grp = idx >> 12;
    int b = ch >> 10, c = ch & 1023, h = c >> 6;
    float P = 1.f, E = 0.f;
#pragma unroll
    for (int i = 0; i < 16; i++) {
        int bn = b * NCHUNK + grp * 16 + i;
        float cc = Cc[(size_t)bn * NHEAD + h];
        E = fmaf(cc, E, Ee[(size_t)bn * HID + c]);
        P *= cc;
    }
    P2[idx] = P; E2[idx] = E;
}
// scan2c': recompute group-prefix carry from P2/E2 (uniform loop per warp), then intra-group carries
__global__ __launch_bounds__(256) void scan2c_kernel(
    const float* __restrict__ Cc, const float* __restrict__ Ee,
    const float* __restrict__ P2, const float* __restrict__ E2,
    float* __restrict__ carry)
{
    int idx = blockIdx.x * 256 + threadIdx.x;
    int ch = idx & 4095, grp = idx >> 12;
    int b = ch >> 10, c = ch & 1023, h = c >> 6;

    // group-prefix carry: identical fmaf chain to the old scan2b
    float car = 0.f;
    for (int gg = 0; gg < grp; gg++)
        car = fmaf(P2[gg * 4096 + ch], car, E2[gg * 4096 + ch]);

#pragma unroll
    for (int i = 0; i < 16; i++) {
        int bn = b * NCHUNK + grp * 16 + i;
        carry[(size_t)bn * HID + c] = car;
        car = fmaf(Cc[(size_t)bn * NHEAD + h], car, Ee[(size_t)bn * HID + c]);
    }
}

// ---------------- scanB: recurrence with carry -> fp16 h (in place) + h_final ----------------
__global__ __launch_bounds__(256) void scanB_kernel(
    const float* __restrict__ a_buf, const float* __restrict__ beta_buf,
    const float* __restrict__ carry,
    __half* __restrict__ xh, float* __restrict__ h_final)
{
    const int unit = threadIdx.x >> 6;
    const int d    = threadIdx.x & 63;
    const int blk  = blockIdx.x * 4 + unit;
    const int h    = blk & 15;
    const int bn   = blk >> 4;
    const int base_pos = bn * CSZ;

    __shared__ float s_cum[4][CSZ], s_inv[4][CSZ], s_beta[4][CSZ];
    __shared__ float s_a[4][CSZ];
    if (d < CSZ) {
        s_a[unit][d]    = a_buf[(size_t)(base_pos + d) * NHEAD + h];
        s_beta[unit][d] = beta_buf[(size_t)(base_pos + d) * NHEAD + h];
    }
    __syncthreads();
    if (d == 0) {
        float c = 1.f;
#pragma unroll
        for (int j = 0; j < CSZ; j++) {
            float cp = c;
            c = c * s_a[unit][j];
            s_cum[unit][j] = c;
            s_inv[unit][j] = (fabsf(cp) > 1e-8f) ? (1.f / cp) : 0.f;
        }
    }
    __syncthreads();

    float Q = carry[(size_t)bn * HID + h * HD + d];
    float hc = 0.f;
#pragma unroll
    for (int j = 0; j < CSZ; j++) {
        size_t idx = (size_t)(base_pos + j) * HID + h * HD + d;
        float bv = s_beta[unit][j] * __half2float(xh[idx]);
        hc = fmaf(s_cum[unit][j], Q, bv);
        xh[idx] = __float2half_rn(hc);
        Q = fmaf(bv, s_inv[unit][j], Q);
    }
    if ((bn & (NCHUNK - 1)) == NCHUNK - 1) {
        int b = bn >> 8;
        h_final[(size_t)b * HID + h * HD + d] = hc;
    }
}

// ---------------- launch ----------------
extern "C" void kernel_launch(void* const* d_in, const int* in_sizes, int n_in,
                              void* d_out, int out_size)
{
    const float* x       = (const float*)d_in[0];
    const float* W_in    = (const float*)d_in[1];
    const float* ln_g    = (const float*)d_in[2];
    const float* ln_b    = (const float*)d_in[3];
    const float* W_gate  = (const float*)d_in[4];
    const float* b_gate  = (const float*)d_in[5];
    const float* eig_raw = (const float*)d_in[6];
    const float* W_out   = (const float*)d_in[7];

    float* out     = (float*)d_out;
    float* h_final = out + (size_t)MROWS * HID;

    __half *Abuf, *Wbuf, *xph;
    float *ab, *bb, *Cc, *Ee, *carry, *P2, *E2;
    cudaGetSymbolAddress((void**)&Abuf,  g_Abuf);
    cudaGetSymbolAddress((void**)&Wbuf,  g_Wbuf);
    cudaGetSymbolAddress((void**)&xph,   g_xph);
    cudaGetSymbolAddress((void**)&ab,    g_a);
    cudaGetSymbolAddress((void**)&bb,    g_beta);
    cudaGetSymbolAddress((void**)&Cc,    g_C);
    cudaGetSymbolAddress((void**)&Ee,    g_E);
    cudaGetSymbolAddress((void**)&carry, g_carry);
    cudaGetSymbolAddress((void**)&P2,    g_P2);
    cudaGetSymbolAddress((void**)&E2,    g_E2);

    cudaFuncSetAttribute(mma_gemm_kernel<true>,  cudaFuncAttributeMaxDynamicSharedMemorySize, GEMM_SMEM);
    cudaFuncSetAttribute(mma_gemm_kernel<false>, cudaFuncAttributeMaxDynamicSharedMemorySize, GEMM_SMEM);
    cudaFuncSetAttribute(gates_mma_kernel, cudaFuncAttributeMaxDynamicSharedMemorySize, GATES_SMEM);

    // 0: fused convert (x + all weights)
    convert_all_kernel<<<(ALL4 + 255) / 256, 256>>>(x, W_in, W_gate, W_out, Abuf, Wbuf);

    // 1: GEMM1 -> xph (fp16)
    mma_gemm_kernel<true><<<dim3(HID / 128, MROWS / 128), 256, GEMM_SMEM>>>(Abuf, Wbuf, nullptr, xph);

    // 2-3: LN -> xn fp16 (in Abuf); gates
    ln_kernel<<<MROWS / 8, 256>>>(xph, ln_g, ln_b, Abuf);
    gates_mma_kernel<<<MROWS / 128, 256, GATES_SMEM>>>(Abuf, Wbuf + WG_OFF, b_gate, eig_raw, ab, bb);

    // 4-7: chunked scan: Cc/Ee -> group totals -> fused carry -> h (in place) + h_final
    scanE_kernel<<<BNCH * NHEAD / 4, 256>>>(ab, bb, Abuf, Cc, Ee);
    scan2a_kernel<<<(BATCH * HID * 16) / 256, 256>>>(Cc, Ee, P2, E2);
    scan2c_kernel<<<(BATCH * HID * 16) / 256, 256>>>(Cc, Ee, P2, E2, carry);
    scanB_kernel<<<BNCH * NHEAD / 4, 256>>>(ab, bb, carry, Abuf, h_final);

    // 8: GEMM2 -> out (fp32)
    mma_gemm_kernel<false><<<dim3(HID / 128, MROWS / 128), 256, GEMM_SMEM>>>(Abuf, Wbuf + WO_OFF, out, nullptr);
}

// round 17
// speedup vs baseline: 1.0279x; 1.0033x over previous
#include <cuda_runtime.h>
#include <cuda_fp16.h>
#include <math.h>
#include <stdint.h>

// ---------------- problem constants ----------------
#define BATCH   4
#define SEQ     4096
#define HID     1024
#define NHEAD   16
#define HD      64
#define CSZ     16
#define MROWS   (BATCH*SEQ)        // 16384
#define NCHUNK  (SEQ/CSZ)          // 256
#define BNCH    (BATCH*NCHUNK)     // 1024
#define KTOT    1024
#define BK      64                 // fp16 K per stage (128 bytes/row)
#define KI      (KTOT/BK)          // 16
#define NSTG    3                  // 96KB -> 2 CTAs/SM
#define STG_BYTES 32768            // A 16KB + B 16KB
#define GEMM_SMEM (NSTG*STG_BYTES)
#define GNSTG   4
#define GATES_STG 12288            // A 8KB (64 rows) + B 4KB (32 rows)
#define GATES_SMEM (GNSTG*GATES_STG) // 48 KB

// weight buffer layout (fp16): W_in | W_gate | W_out
#define WG_OFF   (HID*HID)
#define WO_OFF   (HID*HID + 2*NHEAD*HID)
#define WTOT     (2*HID*HID + 2*NHEAD*HID)

// fused convert partition (float4 indices)
#define XN4      (MROWS*HID/4)
#define WIN4     (HID*HID/4)
#define WG4      (2*NHEAD*HID/4)
#define ALL4     (XN4 + WTOT/4)

// ---------------- scratch ----------------
__device__ __align__(16) __half g_Abuf[(size_t)MROWS*KTOT]; // x -> xn -> h (in place)
__device__ __align__(16) __half g_Wbuf[(size_t)WTOT];
__device__ __align__(16) __half g_xph[(size_t)MROWS*HID];
__device__ float g_a[MROWS*NHEAD];
__device__ float g_beta[MROWS*NHEAD];
__device__ float g_C[BNCH*NHEAD];
__device__ float g_E[BNCH*HID];
__device__ float g_carry[BNCH*HID];
__device__ float g_P2[BATCH*HID*16];
__device__ float g_E2[BATCH*HID*16];

// ---------------- PTX helpers ----------------
__device__ __forceinline__ uint32_t smem_u32(const void* p) {
    uint32_t a;
    asm("{ .reg .u64 t; cvta.to.shared.u64 t, %1; cvt.u32.u64 %0, t; }" : "=r"(a) : "l"(p));
    return a;
}
#define CP_COMMIT() asm volatile("cp.async.commit_group;" ::: "memory")
#define CP_WAIT(N)  asm volatile("cp.async.wait_group %0;" :: "n"(N) : "memory")
__device__ __forceinline__ void cp_async16(uint32_t s, const void* g) {
    asm volatile("cp.async.cg.shared.global [%0], [%1], 16;" :: "r"(s), "l"(g) : "memory");
}
__device__ __forceinline__ void ldsm_x4(uint32_t& r0, uint32_t& r1, uint32_t& r2, uint32_t& r3, uint32_t addr) {
    asm volatile("ldmatrix.sync.aligned.m8n8.x4.shared.b16 {%0,%1,%2,%3}, [%4];"
                 : "=r"(r0), "=r"(r1), "=r"(r2), "=r"(r3) : "r"(addr));
}
__device__ __forceinline__ void mma16816(float& c0, float& c1, float& c2, float& c3,
                                         uint32_t a0, uint32_t a1, uint32_t a2, uint32_t a3,
                                         uint32_t b0, uint32_t b1) {
    asm volatile("mma.sync.aligned.m16n8k16.row.col.f32.f16.f16.f32 "
                 "{%0,%1,%2,%3}, {%4,%5,%6,%7}, {%8,%9}, {%0,%1,%2,%3};"
                 : "+f"(c0), "+f"(c1), "+f"(c2), "+f"(c3)
                 : "r"(a0), "r"(a1), "r"(a2), "r"(a3), "r"(b0), "r"(b1));
}
__device__ __forceinline__ uint32_t swz(uint32_t off) { return off ^ ((off >> 3) & 0x70); }

// ---------------- fused fp32 -> fp16 conversion: x + W_in + W_gate + W_out ----------------
__global__ __launch_bounds__(256) void convert_all_kernel(
    const float* __restrict__ x, const float* __restrict__ Win,
    const float* __restrict__ Wg, const float* __restrict__ Wo,
    __half* __restrict__ Abuf, __half* __restrict__ Wbuf)
{
    int g = blockIdx.x * 256 + threadIdx.x;
    if (g >= ALL4) return;
    const float* src;
    __half* dst;
    int di;
    if (g < XN4) {
        src = x + g * 4; dst = Abuf; di = g;
    } else {
        int e = g - XN4;
        dst = Wbuf; di = e;
        if (e < WIN4)             src = Win + e * 4;
        else if (e < WIN4 + WG4)  src = Wg + (e - WIN4) * 4;
        else                      src = Wo + (e - WIN4 - WG4) * 4;
    }
    float4 v = *reinterpret_cast<const float4*>(src);
    union { __half h[4]; uint2 u; } H;
    H.h[0] = __float2half_rn(v.x);
    H.h[1] = __float2half_rn(v.y);
    H.h[2] = __float2half_rn(v.z);
    H.h[3] = __float2half_rn(v.w);
    reinterpret_cast<uint2*>(dst)[di] = H.u;
}

// ---------------- mma.sync fp16 GEMM: 128x128 tile, 8 warps of 32x64 (R8 config) ----------------
__device__ __forceinline__ void load_stage(const __half* Ag, const __half* Bg,
                                           uint32_t stage_base, int tid, int kit) {
    const __half* Ak = Ag + kit * BK;
    const __half* Bk = Bg + kit * BK;
    uint32_t sa = stage_base;
    uint32_t sbb = stage_base + 16384;
#pragma unroll
    for (int i = 0; i < 4; i++) {
        int u = tid + i * 256;
        int row = u >> 3, c = u & 7;
        uint32_t off = swz((uint32_t)(row * 128 + c * 16));
        cp_async16(sa  + off, Ak + (size_t)row * KTOT + c * 8);
        cp_async16(sbb + off, Bk + (size_t)row * KTOT + c * 8);
    }
}

template<bool HALF_OUT>
__global__ __launch_bounds__(256, 2) void mma_gemm_kernel(
    const __half* __restrict__ A, const __half* __restrict__ B,
    float* __restrict__ C, __half* __restrict__ Ch)
{
    extern __shared__ char smem[];
    const uint32_t sb = smem_u32(smem);
    const int tid = threadIdx.x, wid = tid >> 5, lane = tid & 31;
    const int m0 = blockIdx.y * 128;
    const int n0 = blockIdx.x * 128;
    const int warpM = (wid & 3) * 32;
    const int warpN = (wid >> 2) * 64;

    const __half* Ag = A + (size_t)m0 * KTOT;
    const __half* Bg = B + (size_t)n0 * KTOT;

    float acc[2][8][4];
#pragma unroll
    for (int mi = 0; mi < 2; mi++)
#pragma unroll
        for (int ni = 0; ni < 8; ni++)
#pragma unroll
            for (int q = 0; q < 4; q++) acc[mi][ni][q] = 0.f;

    const int arow = warpM + (lane & 15);
    const int brow = warpN + (lane & 7) + ((lane >> 4) << 3);
    const uint32_t acol_base = (uint32_t)((lane >> 4) << 4);
    const uint32_t bcol_base = (uint32_t)(((lane >> 3) & 1) << 4);

#pragma unroll
    for (int s = 0; s < NSTG - 1; s++) { load_stage(Ag, Bg, sb + s * STG_BYTES, tid, s); CP_COMMIT(); }

    for (int it = 0; it < KI; it++) {
        if (it + NSTG - 1 < KI)
            load_stage(Ag, Bg, sb + ((it + NSTG - 1) % NSTG) * STG_BYTES, tid, it + NSTG - 1);
        CP_COMMIT();
        CP_WAIT(NSTG - 1);
        __syncthreads();

        const uint32_t sa  = sb + (it % NSTG) * STG_BYTES;
        const uint32_t sbb = sa + 16384;
#pragma unroll
        for (int kk = 0; kk < 4; kk++) {
            const uint32_t kByte = (uint32_t)(kk * 32);
            uint32_t a[2][4];
#pragma unroll
            for (int mi = 0; mi < 2; mi++) {
                uint32_t off = swz((uint32_t)((arow + mi * 16) * 128) + kByte + acol_base);
                ldsm_x4(a[mi][0], a[mi][1], a[mi][2], a[mi][3], sa + off);
            }
            uint32_t b[8][2];
#pragma unroll
            for (int nb = 0; nb < 4; nb++) {
                uint32_t off = swz((uint32_t)((brow + nb * 16) * 128) + kByte + bcol_base);
                uint32_t r0, r1, r2, r3;
                ldsm_x4(r0, r1, r2, r3, sbb + off);
                b[nb * 2][0] = r0; b[nb * 2][1] = r1;
                b[nb * 2 + 1][0] = r2; b[nb * 2 + 1][1] = r3;
            }
#pragma unroll
            for (int mi = 0; mi < 2; mi++)
#pragma unroll
                for (int ni = 0; ni < 8; ni++)
                    mma16816(acc[mi][ni][0], acc[mi][ni][1], acc[mi][ni][2], acc[mi][ni][3],
                             a[mi][0], a[mi][1], a[mi][2], a[mi][3], b[ni][0], b[ni][1]);
        }
        __syncthreads();
    }

    const int crow = m0 + warpM + (lane >> 2);
    const int ccol = n0 + warpN + 2 * (lane & 3);
#pragma unroll
    for (int mi = 0; mi < 2; mi++)
#pragma unroll
        for (int ni = 0; ni < 8; ni++) {
            if (HALF_OUT) {
                __half* p0 = Ch + (size_t)(crow + mi * 16) * HID + ccol + ni * 8;
                __half* p1 = p0 + 8 * HID;
                *reinterpret_cast<__half2*>(p0) = __floats2half2_rn(acc[mi][ni][0], acc[mi][ni][1]);
                *reinterpret_cast<__half2*>(p1) = __floats2half2_rn(acc[mi][ni][2], acc[mi][ni][3]);
            } else {
                float* p0 = C + (size_t)(crow + mi * 16) * HID + ccol + ni * 8;
                float* p1 = p0 + 8 * HID;
                *reinterpret_cast<float2*>(p0) = make_float2(acc[mi][ni][0], acc[mi][ni][1]);
                *reinterpret_cast<float2*>(p1) = make_float2(acc[mi][ni][2], acc[mi][ni][3]);
            }
        }
}

// ---------------- LayerNorm (warp per row), fp16 in -> fp16 out ----------------
__global__ __launch_bounds__(256) void ln_kernel(
    const __half* __restrict__ xph, const float* __restrict__ ln_g,
    const float* __restrict__ ln_b, __half* __restrict__ xnh)
{
    int w = threadIdx.x >> 5, lane = threadIdx.x & 31;
    int row = blockIdx.x * 8 + w;
    const uint2* xr = reinterpret_cast<const uint2*>(xph + (size_t)row * HID);
    float v[8][4];
    float s = 0.f, s2 = 0.f;
#pragma unroll
    for (int i = 0; i < 8; i++) {
        union { uint2 u; __half h[4]; } U;
        U.u = xr[lane + 32 * i];
#pragma unroll
        for (int q = 0; q < 4; q++) {
            float f = __half2float(U.h[q]);
            v[i][q] = f;
            s += f; s2 += f * f;
        }
    }
#pragma unroll
    for (int o = 16; o > 0; o >>= 1) {
        s  += __shfl_xor_sync(0xffffffffu, s, o);
        s2 += __shfl_xor_sync(0xffffffffu, s2, o);
    }
    float mu = s * (1.f / HID);
    float rs = rsqrtf(s2 * (1.f / HID) - mu * mu + 1e-5f);
    uint2* xh = reinterpret_cast<uint2*>(xnh + (size_t)row * HID);
#pragma unroll
    for (int i = 0; i < 8; i++) {
        int idx = lane + 32 * i;
        float4 g4 = reinterpret_cast<const float4*>(ln_g)[idx];
        float4 b4 = reinterpret_cast<const float4*>(ln_b)[idx];
        union { uint2 u; __half2 h2[2]; } H;
        H.h2[0] = __floats2half2_rn((v[i][0] - mu) * rs * g4.x + b4.x,
                                    (v[i][1] - mu) * rs * g4.y + b4.y);
        H.h2[1] = __floats2half2_rn((v[i][2] - mu) * rs * g4.z + b4.z,
                                    (v[i][3] - mu) * rs * g4.w + b4.w);
        xh[idx] = H.u;
    }
}

// ---------------- gates via HMMA: 64-row tiles, grid=256 ----------------
// 8 warps: warpM = (wid&3)*16 (one 16-row m-frag), warpN = (wid>>2)*16.
__device__ __forceinline__ void gates_load_stage(const __half* Ag, const __half* Bg,
                                                 uint32_t stage_base, int tid, int kit) {
    const __half* Ak = Ag + kit * BK;
    const __half* Bk = Bg + kit * BK;
    uint32_t sa = stage_base;
    uint32_t sbb = stage_base + 8192;
    {   // A: 64 rows x 128B = 8KB = 512 chunks of 16B; 256 threads x 2
#pragma unroll
        for (int i = 0; i < 2; i++) {
            int u = tid + i * 256;
            int row = u >> 3, c = u & 7;
            uint32_t off = swz((uint32_t)(row * 128 + c * 16));
            cp_async16(sa + off, Ak + (size_t)row * KTOT + c * 8);
        }
    }
    {   // B: 32 rows x 128B = 4KB = 256 chunks
        int row = tid >> 3, c = tid & 7;
        uint32_t off = swz((uint32_t)(row * 128 + c * 16));
        cp_async16(sbb + off, Bk + (size_t)row * KTOT + c * 8);
    }
}

__global__ __launch_bounds__(256) void gates_mma_kernel(
    const __half* __restrict__ A, const __half* __restrict__ Wgh,
    const float* __restrict__ bg, const float* __restrict__ eig,
    float* __restrict__ a_out, float* __restrict__ beta_out)
{
    extern __shared__ char smem[];
    const uint32_t sb = smem_u32(smem);
    const int tid = threadIdx.x, wid = tid >> 5, lane = tid & 31;
    const int m0 = blockIdx.x * 64;
    const int warpM = (wid & 3) * 16;
    const int warpN = (wid >> 2) * 16;

    const __half* Ag = A + (size_t)m0 * KTOT;

    float acc[2][4];
#pragma unroll
    for (int ni = 0; ni < 2; ni++)
#pragma unroll
        for (int q = 0; q < 4; q++) acc[ni][q] = 0.f;

    const int arow = warpM + (lane & 15);
    const int brow = warpN + (lane & 7) + ((lane >> 4) << 3);
    const uint32_t acol_base = (uint32_t)((lane >> 4) << 4);
    const uint32_t bcol_base = (uint32_t)(((lane >> 3) & 1) << 4);

#pragma unroll
    for (int s = 0; s < GNSTG - 1; s++) { gates_load_stage(Ag, Wgh, sb + s * GATES_STG, tid, s); CP_COMMIT(); }

    for (int it = 0; it < KI; it++) {
        if (it + GNSTG - 1 < KI)
            gates_load_stage(Ag, Wgh, sb + ((it + GNSTG - 1) & 3) * GATES_STG, tid, it + GNSTG - 1);
        CP_COMMIT();
        CP_WAIT(GNSTG - 1);
        __syncthreads();

        const uint32_t sa  = sb + (it & 3) * GATES_STG;
        const uint32_t sbb = sa + 8192;
#pragma unroll
        for (int kk = 0; kk < 4; kk++) {
            const uint32_t kByte = (uint32_t)(kk * 32);
            uint32_t a0, a1, a2, a3;
            {
                uint32_t off = swz((uint32_t)(arow * 128) + kByte + acol_base);
                ldsm_x4(a0, a1, a2, a3, sa + off);
            }
            uint32_t b0, b1, b2, b3;
            {
                uint32_t off = swz((uint32_t)(brow * 128) + kByte + bcol_base);
                ldsm_x4(b0, b1, b2, b3, sbb + off);
            }
            mma16816(acc[0][0], acc[0][1], acc[0][2], acc[0][3], a0, a1, a2, a3, b0, b1);
            mma16816(acc[1][0], acc[1][1], acc[1][2], acc[1][3], a0, a1, a2, a3, b2, b3);
        }
        __syncthreads();
    }

    const int crow = m0 + warpM + (lane >> 2);
    const int ccol0 = warpN + 2 * (lane & 3);
#pragma unroll
    for (int ni = 0; ni < 2; ni++) {
        int g0 = ccol0 + ni * 8;
#pragma unroll
        for (int q = 0; q < 4; q++) {
            int g = g0 + (q & 1);
            int row = crow + ((q >> 1) << 3);
            float sg = 1.f / (1.f + expf(-(acc[ni][q] + bg[g])));
            if (g < 16) a_out[(size_t)row * NHEAD + g] = tanhf(eig[g]) * sg;
            else        beta_out[(size_t)row * NHEAD + (g - 16)] = sg;
        }
    }
}

// ---------------- scanE: per-chunk Cc/Ee only (4 units per block) ----------------
__global__ __launch_bounds__(256) void scanE_kernel(
    const float* __restrict__ a_buf, const float* __restrict__ beta_buf,
    const __half* __restrict__ xnh,
    float* __restrict__ Cc, float* __restrict__ Ee)
{
    const int unit = threadIdx.x >> 6;
    const int d    = threadIdx.x & 63;
    const int blk  = blockIdx.x * 4 + unit;
    const int h    = blk & 15;
    const int bn   = blk >> 4;
    const int base_pos = bn * CSZ;

    __shared__ float s_cum[4][CSZ], s_inv[4][CSZ], s_beta[4][CSZ];
    __shared__ float s_a[4][CSZ];
    if (d < CSZ) {
        s_a[unit][d]    = a_buf[(size_t)(base_pos + d) * NHEAD + h];
        s_beta[unit][d] = beta_buf[(size_t)(base_pos + d) * NHEAD + h];
    }
    __syncthreads();
    if (d == 0) {
        float c = 1.f;
#pragma unroll
        for (int j = 0; j < CSZ; j++) {
            float cp = c;
            c = c * s_a[unit][j];
            s_cum[unit][j] = c;
            s_inv[unit][j] = (fabsf(cp) > 1e-8f) ? (1.f / cp) : 0.f;
        }
    }
    __syncthreads();

    float Q = 0.f, hc = 0.f;
#pragma unroll
    for (int j = 0; j < CSZ; j++) {
        size_t idx = (size_t)(base_pos + j) * HID + h * HD + d;
        float bv = s_beta[unit][j] * __half2float(xnh[idx]);
        hc = fmaf(s_cum[unit][j], Q, bv);
        Q = fmaf(bv, s_inv[unit][j], Q);
    }
    Ee[(size_t)bn * HID + h * HD + d] = hc;
    if (d == 0) Cc[(size_t)bn * NHEAD + h] = s_cum[unit][CSZ - 1];
}

// ---------------- scan pass 2: group totals, then fused carry ----------------
__global__ __launch_bounds__(256) void scan2a_kernel(
    const float* __restrict__ Cc, const float* __restrict__ Ee,
    float* __restrict__ P2, float* __restrict__ E2)
{
    int idx = blockIdx.x * 256 + threadIdx.x;
    int ch = idx & 4095, grp = idx >> 12;
    int b = ch >> 10, c = ch & 1023, h = c >> 6;
    float P = 1.f, E = 0.f;
#pragma unroll
    for (int i = 0; i < 16; i++) {
        int bn = b * NCHUNK + grp * 16 + i;
        float cc = Cc[(size_t)bn * NHEAD + h];
        E = fmaf(cc, E, Ee[(size_t)bn * HID + c]);
        P *= cc;
    }
    P2[idx] = P; E2[idx] = E;
}
__global__ __launch_bounds__(256) void scan2c_kernel(
    const float* __restrict__ Cc, const float* __restrict__ Ee,
    const float* __restrict__ P2, const float* __restrict__ E2,
    float* __restrict__ carry)
{
    int idx = blockIdx.x * 256 + threadIdx.x;
    int ch = idx & 4095, grp = idx >> 12;
    int b = ch >> 10, c = ch & 1023, h = c >> 6;

    float car = 0.f;
    for (int gg = 0; gg < grp; gg++)
        car = fmaf(P2[gg * 4096 + ch], car, E2[gg * 4096 + ch]);

#pragma unroll
    for (int i = 0; i < 16; i++) {
        int bn = b * NCHUNK + grp * 16 + i;
        carry[(size_t)bn * HID + c] = car;
        car = fmaf(Cc[(size_t)bn * NHEAD + h], car, Ee[(size_t)bn * HID + c]);
    }
}

// ---------------- scanB: recurrence with carry -> fp16 h (in place) + h_final ----------------
__global__ __launch_bounds__(256) void scanB_kernel(
    const float* __restrict__ a_buf, const float* __restrict__ beta_buf,
    const float* __restrict__ carry,
    __half* __restrict__ xh, float* __restrict__ h_final)
{
    const int unit = threadIdx.x >> 6;
    const int d    = threadIdx.x & 63;
    const int blk  = blockIdx.x * 4 + unit;
    const int h    = blk & 15;
    const int bn   = blk >> 4;
    const int base_pos = bn * CSZ;

    __shared__ float s_cum[4][CSZ], s_inv[4][CSZ], s_beta[4][CSZ];
    __shared__ float s_a[4][CSZ];
    if (d < CSZ) {
        s_a[unit][d]    = a_buf[(size_t)(base_pos + d) * NHEAD + h];
        s_beta[unit][d] = beta_buf[(size_t)(base_pos + d) * NHEAD + h];
    }
    __syncthreads();
    if (d == 0) {
        float c = 1.f;
#pragma unroll
        for (int j = 0; j < CSZ; j++) {
            float cp = c;
            c = c * s_a[unit][j];
            s_cum[unit][j] = c;
            s_inv[unit][j] = (fabsf(cp) > 1e-8f) ? (1.f / cp) : 0.f;
        }
    }
    __syncthreads();

    float Q = carry[(size_t)bn * HID + h * HD + d];
    float hc = 0.f;
#pragma unroll
    for (int j = 0; j < CSZ; j++) {
        size_t idx = (size_t)(base_pos + j) * HID + h * HD + d;
        float bv = s_beta[unit][j] * __half2float(xh[idx]);
        hc = fmaf(s_cum[unit][j], Q, bv);
        xh[idx] = __float2half_rn(hc);
        Q = fmaf(bv, s_inv[unit][j], Q);
    }
    if ((bn & (NCHUNK - 1)) == NCHUNK - 1) {
        int b = bn >> 8;
        h_final[(size_t)b * HID + h * HD + d] = hc;
    }
}

// ---------------- launch ----------------
extern "C" void kernel_launch(void* const* d_in, const int* in_sizes, int n_in,
                              void* d_out, int out_size)
{
    const float* x       = (const float*)d_in[0];
    const float* W_in    = (const float*)d_in[1];
    const float* ln_g    = (const float*)d_in[2];
    const float* ln_b    = (const float*)d_in[3];
    const float* W_gate  = (const float*)d_in[4];
    const float* b_gate  = (const float*)d_in[5];
    const float* eig_raw = (const float*)d_in[6];
    const float* W_out   = (const float*)d_in[7];

    float* out     = (float*)d_out;
    float* h_final = out + (size_t)MROWS * HID;

    __half *Abuf, *Wbuf, *xph;
    float *ab, *bb, *Cc, *Ee, *carry, *P2, *E2;
    cudaGetSymbolAddress((void**)&Abuf,  g_Abuf);
    cudaGetSymbolAddress((void**)&Wbuf,  g_Wbuf);
    cudaGetSymbolAddress((void**)&xph,   g_xph);
    cudaGetSymbolAddress((void**)&ab,    g_a);
    cudaGetSymbolAddress((void**)&bb,    g_beta);
    cudaGetSymbolAddress((void**)&Cc,    g_C);
    cudaGetSymbolAddress((void**)&Ee,    g_E);
    cudaGetSymbolAddress((void**)&carry, g_carry);
    cudaGetSymbolAddress((void**)&P2,    g_P2);
    cudaGetSymbolAddress((void**)&E2,    g_E2);

    cudaFuncSetAttribute(mma_gemm_kernel<true>,  cudaFuncAttributeMaxDynamicSharedMemorySize, GEMM_SMEM);
    cudaFuncSetAttribute(mma_gemm_kernel<false>, cudaFuncAttributeMaxDynamicSharedMemorySize, GEMM_SMEM);
    cudaFuncSetAttribute(gates_mma_kernel, cudaFuncAttributeMaxDynamicSharedMemorySize, GATES_SMEM);

    // 0: fused convert (x + all weights)
    convert_all_kernel<<<(ALL4 + 255) / 256, 256>>>(x, W_in, W_gate, W_out, Abuf, Wbuf);

    // 1: GEMM1 -> xph (fp16)
    mma_gemm_kernel<true><<<dim3(HID / 128, MROWS / 128), 256, GEMM_SMEM>>>(Abuf, Wbuf, nullptr, xph);

    // 2-3: LN -> xn fp16 (in Abuf); gates (64-row tiles, grid 256)
    ln_kernel<<<MROWS / 8, 256>>>(xph, ln_g, ln_b, Abuf);
    gates_mma_kernel<<<MROWS / 64, 256, GATES_SMEM>>>(Abuf, Wbuf + WG_OFF, b_gate, eig_raw, ab, bb);

    // 4-7: chunked scan: Cc/Ee -> group totals -> fused carry -> h (in place) + h_final
    scanE_kernel<<<BNCH * NHEAD / 4, 256>>>(ab, bb, Abuf, Cc, Ee);
    scan2a_kernel<<<(BATCH * HID * 16) / 256, 256>>>(Cc, Ee, P2, E2);
    scan2c_kernel<<<(BATCH * HID * 16) / 256, 256>>>(Cc, Ee, P2, E2, carry);
    scanB_kernel<<<BNCH * NHEAD / 4, 256>>>(ab, bb, carry, Abuf, h_final);

    // 8: GEMM2 -> out (fp32)
    mma_gemm_kernel<false><<<dim3(HID / 128, MROWS / 128), 256, GEMM_SMEM>>>(Abuf, Wbuf + WO_OFF, out, nullptr);
}